// round 8
// baseline (speedup 1.0000x reference)
#include <cuda_runtime.h>
#include <cuda_bf16.h>
#include <math.h>
#include <stdint.h>

#define B_  16
#define N_  1024
#define FIN 128
#define FO  64
#define ALPHA_ 0.2f

// Scratch (device globals: no allocation allowed)
__device__ float  g_hs[B_ * 16 * 64 * 72];    // tf32 h, tiled+padded [b][tile][j][o(72)]
__device__ float2 g_pq1[B_ * N_];             // {exp(s1), exp(a*s1)}
__device__ float2 g_pq2[B_ * N_];             // {exp(s2), exp(a*s2)}

__device__ __forceinline__ float to_tf32(float x) {
    float r;
    asm("cvt.rna.tf32.f32 %0, %1;" : "=f"(r) : "f"(x));
    return r;
}
__device__ __forceinline__ void mma_tf32(float* d, const uint32_t* a,
                                         uint32_t b0, uint32_t b1) {
    asm volatile(
        "mma.sync.aligned.m16n8k8.row.col.f32.tf32.tf32.f32 "
        "{%0,%1,%2,%3}, {%4,%5,%6,%7}, {%8,%9}, {%0,%1,%2,%3};"
        : "+f"(d[0]), "+f"(d[1]), "+f"(d[2]), "+f"(d[3])
        : "r"(a[0]), "r"(a[1]), "r"(a[2]), "r"(a[3]), "r"(b0), "r"(b1));
}

// k_attn smem layout; accbuf[64][72] reuses [0, 18432) after the main loop
#define ADJP_OFF 0          // uint32 adjP[64][4] = 1024 B (bitmasks)
#define HS_OFF   1024       // float hs[64][72]   = 18432 B
#define PQ2_OFF  19456      // float2 pq2s[1024]  = 8192 B
#define ZP2_OFF  27648      // float zp2[4][64]   = 1024 B
#define ZS_OFF   28672      // float zs[64]       = 256 B
#define SMEM_ATTN 28928

#define SMEM_HG  66048      // sI 32K + sW 32K + sA 512

// ---------------------------------------------------------------------------
// Kernel 1: h = inp @ W  -> g_hs (tf32, padded stride 72) + fused scores.
// CTA: 64 rows x 64 outs, 256 threads; thread = 4 rows x 4 outs.
// ---------------------------------------------------------------------------
__global__ __launch_bounds__(256) void k_h_gemm(const float* __restrict__ inp,
                                                const float* __restrict__ W,
                                                const float* __restrict__ a) {
    extern __shared__ char sm1[];
    float* sI = (float*)sm1;             // [64][128]
    float* sW = (float*)(sm1 + 32768);   // [128][64]
    float* sA = (float*)(sm1 + 65536);   // [128]

    const int b    = blockIdx.y;
    const int bx   = blockIdx.x;         // == tile index (64 rows per tile)
    const int row0 = bx * 64;
    const int t    = threadIdx.x;

#pragma unroll
    for (int k = 0; k < 8; k++)
        ((float4*)sW)[t + k * 256] = ((const float4*)W)[t + k * 256];
    const float4* ip = (const float4*)(inp + ((size_t)b * N_ + row0) * FIN);
#pragma unroll
    for (int k = 0; k < 8; k++)
        ((float4*)sI)[t + k * 256] = ip[t + k * 256];
    if (t < 128) sA[t] = a[t];
    __syncthreads();

    const int ot = t & 15;
    const int rt = t >> 4;
    const int lane = t & 31;

    float acc[4][4];
#pragma unroll
    for (int r = 0; r < 4; r++)
#pragma unroll
        for (int c = 0; c < 4; c++) acc[r][c] = 0.f;

#pragma unroll 4
    for (int k = 0; k < FIN; k++) {
        const float4 w4 = *(const float4*)(sW + k * FO + ot * 4);
#pragma unroll
        for (int r = 0; r < 4; r++) {
            const float iv = sI[(rt * 4 + r) * FIN + k];
            acc[r][0] += iv * w4.x;
            acc[r][1] += iv * w4.y;
            acc[r][2] += iv * w4.z;
            acc[r][3] += iv * w4.w;
        }
    }

    // store tf32 h into padded tiled layout
#pragma unroll
    for (int r = 0; r < 4; r++) {
        float4 wq;
        wq.x = to_tf32(acc[r][0]);
        wq.y = to_tf32(acc[r][1]);
        wq.z = to_tf32(acc[r][2]);
        wq.w = to_tf32(acc[r][3]);
        float* op = g_hs + ((size_t)(b * 16 + bx) * 64 + rt * 4 + r) * 72 + ot * 4;
        *(float4*)op = wq;
    }

    // fused scores
    float s1p[4], s2p[4];
#pragma unroll
    for (int r = 0; r < 4; r++) {
        float v1 = 0.f, v2 = 0.f;
#pragma unroll
        for (int c = 0; c < 4; c++) {
            v1 += acc[r][c] * sA[ot * 4 + c];
            v2 += acc[r][c] * sA[64 + ot * 4 + c];
        }
        s1p[r] = v1; s2p[r] = v2;
    }
#pragma unroll
    for (int off = 8; off > 0; off >>= 1) {
#pragma unroll
        for (int r = 0; r < 4; r++) {
            s1p[r] += __shfl_xor_sync(0xffffffffu, s1p[r], off);
            s2p[r] += __shfl_xor_sync(0xffffffffu, s2p[r], off);
        }
    }
    if ((lane & 15) == 0) {
#pragma unroll
        for (int r = 0; r < 4; r++) {
            const int gi = b * N_ + row0 + rt * 4 + r;
            g_pq1[gi] = make_float2(__expf(s1p[r]), __expf(ALPHA_ * s1p[r]));
            g_pq2[gi] = make_float2(__expf(s2p[r]), __expf(ALPHA_ * s2p[r]));
        }
    }
}

// ---------------------------------------------------------------------------
// Kernel 2: attention via mma.sync tf32; w computed directly in fragment regs.
// CTA: 64 i x 64 o, 512 thr, 16 warps = 4k x 2m x 2n, warp tile 32x32x16.
// adj staged as bitmasks; h staged via linear (conflict-free) bulk copy.
// ---------------------------------------------------------------------------
__global__ __launch_bounds__(512, 2) void k_attn(const int* __restrict__ adj,
                                                 float* __restrict__ out) {
    extern __shared__ char sm[];
    uint32_t* adjP = (uint32_t*)(sm + ADJP_OFF);   // [64][4] bit words
    float*  hs   = (float*)(sm + HS_OFF);          // [64][72]
    float2* pq2s = (float2*)(sm + PQ2_OFF);        // [1024]
    float*  zp2  = (float*)(sm + ZP2_OFF);         // [4][64]
    float*  zs   = (float*)(sm + ZS_OFF);          // [64]
    float*  accbuf = (float*)sm;                   // [64][72] (reuse after loop)

    const int b  = blockIdx.y;
    const int i0 = blockIdx.x * 64;
    const int t  = threadIdx.x;

    for (int idx = t; idx < N_; idx += 512)
        pq2s[idx] = g_pq2[b * N_ + idx];

    // gen mapping: row ir (0..63), 8 j's at jh
    const int ir = t & 63;
    const int jh = (t >> 6) * 8;
    const int* adjrow = adj + (size_t)b * N_ * N_ + (size_t)(i0 + ir) * N_ + jh;

    // mma mapping
    const int wid  = t >> 5;
    const int lane = t & 31;
    const int g    = lane >> 2;
    const int tid4 = lane & 3;
    const int kq   = wid >> 2;
    const int m0   = ((wid >> 1) & 1) * 32;
    const int n0   = (wid & 1) * 32;
    const int nq   = wid & 1;
    const int kbase = kq * 16;
    const int kwq   = kq >> 1;           // adj word index (0/1)
    const int kbit  = (kq & 1) * 16;     // bit base within word

    // per-lane row constants (4 rows: m0+g+8u)
    float p1r[4], q1r[4];
#pragma unroll
    for (int u = 0; u < 4; u++) {
        const float2 pq = g_pq1[b * N_ + i0 + m0 + g + 8 * u];
        p1r[u] = pq.x; q1r[u] = pq.y;
    }

    float acc[2][4][4];
#pragma unroll
    for (int mt = 0; mt < 2; mt++)
#pragma unroll
        for (int nf = 0; nf < 4; nf++)
#pragma unroll
            for (int c = 0; c < 4; c++) acc[mt][nf][c] = 0.f;
    float zac[4] = {0.f, 0.f, 0.f, 0.f};

    const float4* hsg = (const float4*)(g_hs + (size_t)b * 16 * 4608);

    __syncthreads();

    for (int tile = 0; tile < 16; tile++) {
        __syncthreads();   // prev MMA done reading adjP/hs

        // ---- gen: adj bits + h bulk copy ----
        const int4* ap = (const int4*)(adjrow + tile * 64);
        const int4 a0 = ap[0];
        const int4 a1 = ap[1];
        const float4* src = hsg + tile * 1152;
        float4 h0 = src[t];
        float4 h1 = src[t + 512];
        float4 h2;
        if (t < 128) h2 = src[t + 1024];

        uint32_t m = (a0.x > 0) | ((a0.y > 0) << 1) | ((a0.z > 0) << 2) |
                     ((a0.w > 0) << 3) | ((a1.x > 0) << 4) | ((a1.y > 0) << 5) |
                     ((a1.z > 0) << 6) | ((a1.w > 0) << 7);
        ((uint8_t*)adjP)[ir * 16 + (jh >> 3)] = (uint8_t)m;

        ((float4*)hs)[t]       = h0;
        ((float4*)hs)[t + 512] = h1;
        if (t < 128) ((float4*)hs)[t + 1024] = h2;

        __syncthreads();

        // ---- MMA phase: w in fragment registers ----
        uint32_t aw[4];
#pragma unroll
        for (int u = 0; u < 4; u++)
            aw[u] = adjP[(m0 + g + 8 * u) * 4 + kwq];

#pragma unroll
        for (int s = 0; s < 2; s++) {
            const int k0 = kbase + 8 * s;
            const int kt = k0 + tid4;
            const float2 pqa = pq2s[tile * 64 + kt];
            const float2 pqb = pq2s[tile * 64 + kt + 4];
            const int bA = kbit + 8 * s + tid4;
            const int bB = bA + 4;

            float wA[4], wB[4];
#pragma unroll
            for (int u = 0; u < 4; u++) {
                float va = fmaxf(p1r[u] * pqa.x, q1r[u] * pqa.y);
                wA[u] = ((aw[u] >> bA) & 1u) ? va : 0.f;
                zac[u] += wA[u];
                float vb = fmaxf(p1r[u] * pqb.x, q1r[u] * pqb.y);
                wB[u] = ((aw[u] >> bB) & 1u) ? vb : 0.f;
                zac[u] += wB[u];
            }
            uint32_t A0[4], A1[4];
            A0[0] = __float_as_uint(to_tf32(wA[0]));
            A0[1] = __float_as_uint(to_tf32(wA[1]));
            A0[2] = __float_as_uint(to_tf32(wB[0]));
            A0[3] = __float_as_uint(to_tf32(wB[1]));
            A1[0] = __float_as_uint(to_tf32(wA[2]));
            A1[1] = __float_as_uint(to_tf32(wA[3]));
            A1[2] = __float_as_uint(to_tf32(wB[2]));
            A1[3] = __float_as_uint(to_tf32(wB[3]));

#pragma unroll
            for (int nf = 0; nf < 4; nf++) {
                const int c0 = n0 + nf * 8 + g;
                const uint32_t b0 = __float_as_uint(hs[kt * 72 + c0]);
                const uint32_t b1 = __float_as_uint(hs[(kt + 4) * 72 + c0]);
                mma_tf32(acc[0][nf], A0, b0, b1);
                mma_tf32(acc[1][nf], A1, b0, b1);
            }
        }
    }

    // ---- z: quad-reduce (tid4), dedupe nq, per-kq slots ----
#pragma unroll
    for (int u = 0; u < 4; u++) {
        zac[u] += __shfl_xor_sync(0xffffffffu, zac[u], 1);
        zac[u] += __shfl_xor_sync(0xffffffffu, zac[u], 2);
    }
    if (nq == 0 && tid4 == 0) {
#pragma unroll
        for (int u = 0; u < 4; u++)
            zp2[kq * 64 + m0 + g + 8 * u] = zac[u];
    }
    __syncthreads();   // zp2 visible; all MMA done -> accbuf region free
    if (t < 64) zs[t] = (zp2[t] + zp2[64 + t]) + (zp2[128 + t] + zp2[192 + t]);

    // ---- k-reduction across the 4 k-slices into accbuf ----
#pragma unroll
    for (int ph = 0; ph < 4; ph++) {
        if (ph > 0) __syncthreads();
        if (kq == ph) {
#pragma unroll
            for (int mt = 0; mt < 2; mt++) {
#pragma unroll
                for (int nf = 0; nf < 4; nf++) {
                    const int rA = m0 + mt * 16 + g;
                    const int cc = n0 + nf * 8 + 2 * tid4;
                    float2* pA = (float2*)(accbuf + rA * 72 + cc);
                    float2* pB = (float2*)(accbuf + (rA + 8) * 72 + cc);
                    if (ph == 0) {
                        *pA = make_float2(acc[mt][nf][0], acc[mt][nf][1]);
                        *pB = make_float2(acc[mt][nf][2], acc[mt][nf][3]);
                    } else {
                        float2 vA = *pA, vB = *pB;
                        vA.x += acc[mt][nf][0]; vA.y += acc[mt][nf][1];
                        vB.x += acc[mt][nf][2]; vB.y += acc[mt][nf][3];
                        *pA = vA; *pB = vB;
                    }
                }
            }
        }
    }
    __syncthreads();

    // ---- final: normalize + ELU + store ----
    {
        const int row = t >> 3;
        const int c0  = (t & 7) * 8;
        const float inv = 1.f / zs[row];
        const float* srcp = accbuf + row * 72 + c0;
        float4 r;
        float v;
        float4 x = *(const float4*)srcp;
        v = x.x * inv; r.x = (v > 0.f) ? v : expm1f(v);
        v = x.y * inv; r.y = (v > 0.f) ? v : expm1f(v);
        v = x.z * inv; r.z = (v > 0.f) ? v : expm1f(v);
        v = x.w * inv; r.w = (v > 0.f) ? v : expm1f(v);
        float4* op = (float4*)(out + ((size_t)(b * N_ + i0 + row)) * FO + c0);
        op[0] = r;
        x = *(const float4*)(srcp + 4);
        v = x.x * inv; r.x = (v > 0.f) ? v : expm1f(v);
        v = x.y * inv; r.y = (v > 0.f) ? v : expm1f(v);
        v = x.z * inv; r.z = (v > 0.f) ? v : expm1f(v);
        v = x.w * inv; r.w = (v > 0.f) ? v : expm1f(v);
        op[1] = r;
    }
}

// ---------------------------------------------------------------------------
extern "C" void kernel_launch(void* const* d_in, const int* in_sizes, int n_in,
                              void* d_out, int out_size) {
    const float* inp = (const float*)d_in[0];   // (16,1024,128) f32
    const int*   adj = (const int*)d_in[1];     // (16,1024,1024) i32
    const float* W   = (const float*)d_in[2];   // (128,64) f32
    const float* a   = (const float*)d_in[3];   // (128,1) f32
    float* out = (float*)d_out;                 // (16,1024,64) f32

    static int init = 0;
    if (!init) {
        cudaFuncSetAttribute(k_h_gemm, cudaFuncAttributeMaxDynamicSharedMemorySize,
                             SMEM_HG);
        cudaFuncSetAttribute(k_attn, cudaFuncAttributeMaxDynamicSharedMemorySize,
                             SMEM_ATTN);
        init = 1;
    }

    k_h_gemm<<<dim3(N_ / 64, B_), 256, SMEM_HG>>>(inp, W, a);
    k_attn<<<dim3(N_ / 64, B_), 512, SMEM_ATTN>>>(adj, out);
}

// round 9
// speedup vs baseline: 1.3877x; 1.3877x over previous
#include <cuda_runtime.h>
#include <cuda_bf16.h>
#include <math.h>
#include <stdint.h>

#define B_  16
#define N_  1024
#define FIN 128
#define FO  64
#define ALPHA_ 0.2f

// Scratch (device globals: no allocation allowed)
__device__ float g_h[B_ * N_ * FO];           // 4 MB  [b][j][o]
__device__ float g_p1[B_ * N_], g_q1[B_ * N_];
__device__ float g_p2[B_ * N_], g_q2[B_ * N_];

__device__ __forceinline__ float to_tf32(float x) {
    float r;
    asm("cvt.rna.tf32.f32 %0, %1;" : "=f"(r) : "f"(x));
    return r;
}
__device__ __forceinline__ void mma_tf32(float* d, const uint32_t* a,
                                         uint32_t b0, uint32_t b1) {
    asm volatile(
        "mma.sync.aligned.m16n8k8.row.col.f32.tf32.tf32.f32 "
        "{%0,%1,%2,%3}, {%4,%5,%6,%7}, {%8,%9}, {%0,%1,%2,%3};"
        : "+f"(d[0]), "+f"(d[1]), "+f"(d[2]), "+f"(d[3])
        : "r"(a[0]), "r"(a[1]), "r"(a[2]), "r"(a[3]), "r"(b0), "r"(b1));
}

// k_attn smem layout (accbuf[64][72] reuses [0, 18432) after the main loop)
#define HS_OFF   17408      // float hs[64][72] = 18432
#define P2_OFF   35840      // float p2s[1024]
#define Q2_OFF   39936
#define ZS_OFF   44032      // float zs[64]
#define SMEM_ATTN 44288

#define SMEM_HG  66048      // sI 32K + sW 32K + sA 512

// ---------------------------------------------------------------------------
// Kernel 1: h = inp @ W, fused with per-node exps (p1,q1,p2,q2).
// ---------------------------------------------------------------------------
__global__ __launch_bounds__(256) void k_h_gemm(const float* __restrict__ inp,
                                                const float* __restrict__ W,
                                                const float* __restrict__ a) {
    extern __shared__ char sm1[];
    float* sI = (float*)sm1;             // [64][128]
    float* sW = (float*)(sm1 + 32768);   // [128][64]
    float* sA = (float*)(sm1 + 65536);   // [128]

    const int b    = blockIdx.y;
    const int row0 = blockIdx.x * 64;
    const int t    = threadIdx.x;

#pragma unroll
    for (int k = 0; k < 8; k++)
        ((float4*)sW)[t + k * 256] = ((const float4*)W)[t + k * 256];
    const float4* ip = (const float4*)(inp + ((size_t)b * N_ + row0) * FIN);
#pragma unroll
    for (int k = 0; k < 8; k++)
        ((float4*)sI)[t + k * 256] = ip[t + k * 256];
    if (t < 128) sA[t] = a[t];
    __syncthreads();

    const int ot = t & 15;
    const int rt = t >> 4;
    const int lane = t & 31;

    float acc[4][4];
#pragma unroll
    for (int r = 0; r < 4; r++)
#pragma unroll
        for (int c = 0; c < 4; c++) acc[r][c] = 0.f;

#pragma unroll 4
    for (int k = 0; k < FIN; k++) {
        const float4 w4 = *(const float4*)(sW + k * FO + ot * 4);
#pragma unroll
        for (int r = 0; r < 4; r++) {
            const float iv = sI[(rt * 4 + r) * FIN + k];
            acc[r][0] += iv * w4.x;
            acc[r][1] += iv * w4.y;
            acc[r][2] += iv * w4.z;
            acc[r][3] += iv * w4.w;
        }
    }

#pragma unroll
    for (int r = 0; r < 4; r++) {
        float* op = g_h + ((size_t)b * N_ + row0 + rt * 4 + r) * FO + ot * 4;
        *(float4*)op = make_float4(acc[r][0], acc[r][1], acc[r][2], acc[r][3]);
    }

    float s1p[4], s2p[4];
#pragma unroll
    for (int r = 0; r < 4; r++) {
        float v1 = 0.f, v2 = 0.f;
#pragma unroll
        for (int c = 0; c < 4; c++) {
            v1 += acc[r][c] * sA[ot * 4 + c];
            v2 += acc[r][c] * sA[64 + ot * 4 + c];
        }
        s1p[r] = v1; s2p[r] = v2;
    }
#pragma unroll
    for (int off = 8; off > 0; off >>= 1) {
#pragma unroll
        for (int r = 0; r < 4; r++) {
            s1p[r] += __shfl_xor_sync(0xffffffffu, s1p[r], off);
            s2p[r] += __shfl_xor_sync(0xffffffffu, s2p[r], off);
        }
    }
    if ((lane & 15) == 0) {
#pragma unroll
        for (int r = 0; r < 4; r++) {
            const int gi = b * N_ + row0 + rt * 4 + r;
            g_p1[gi] = __expf(s1p[r]);
            g_q1[gi] = __expf(ALPHA_ * s1p[r]);
            g_p2[gi] = __expf(s2p[r]);
            g_q2[gi] = __expf(ALPHA_ * s2p[r]);
        }
    }
}

// ---------------------------------------------------------------------------
// Kernel 2: attention via mma.sync tf32, k-split warp specialization.
// CTA: 64 i x 64 o, 512 thr, 16 warps = 4k x 2m x 2n, warp tile 32x32x16.
// Gen mapping COALESCED: thread -> (row t>>3, 8 j's at (t&7)*8):
//   each warp-LDG of adj touches 4 cache lines (was 32).
// w_ij = adj ? max(p1*p2, q1*q2) : 0 ; z accumulated exactly in fp32.
// ---------------------------------------------------------------------------
__global__ __launch_bounds__(512, 2) void k_attn(const int* __restrict__ adj,
                                                 float* __restrict__ out) {
    extern __shared__ char sm[];
    float* ws  = (float*)sm;               // [64][68]
    float* hs  = (float*)(sm + HS_OFF);    // [64][72]
    float* p2s = (float*)(sm + P2_OFF);
    float* q2s = (float*)(sm + Q2_OFF);
    float* zs  = (float*)(sm + ZS_OFF);
    float* accbuf = (float*)sm;            // [64][72], reuses ws/hs after loop

    const int b  = blockIdx.y;
    const int i0 = blockIdx.x * 64;
    const int t  = threadIdx.x;

    for (int idx = t; idx < N_; idx += 512) {
        const int gj = b * N_ + idx;
        p2s[idx] = g_p2[gj]; q2s[idx] = g_q2[gj];
    }

    // gen mapping: row ir = t>>3 (0..63), j-block jh = (t&7)*8 (coalesced)
    const int ir = t >> 3;
    const int jh = (t & 7) * 8;
    const int gi = b * N_ + i0 + ir;
    const float p1r = g_p1[gi], q1r = g_q1[gi];
    const int* adjrow = adj + (size_t)b * N_ * N_ + (size_t)(i0 + ir) * N_ + jh;

    // mma mapping: wid = kq*4 + mq*2 + nq ; warp tile 32x32, k-slice 16
    const int wid   = t >> 5;
    const int lane  = t & 31;
    const int g     = lane >> 2;
    const int tid4  = lane & 3;
    const int kq    = wid >> 2;
    const int m0    = ((wid >> 1) & 1) * 32;
    const int n0    = (wid & 1) * 32;
    const int kbase = kq * 16;

    float acc[2][4][4];
#pragma unroll
    for (int mt = 0; mt < 2; mt++)
#pragma unroll
        for (int nf = 0; nf < 4; nf++)
#pragma unroll
            for (int c = 0; c < 4; c++) acc[mt][nf][c] = 0.f;

    const float4* hb4 = (const float4*)(g_h + (size_t)b * N_ * FO);
    float zacc = 0.f;

    for (int tile = 0; tile < 16; tile++) {
        __syncthreads();   // prev MMA done reading ws/hs (tile0: tables ready)

        // issue global loads first (adj coalesced + h tile)
        const int4* ap = (const int4*)(adjrow + tile * 64);
        const int4 av0 = ap[0];
        const int4 av1 = ap[1];
        float4 hv0 = hb4[tile * 1024 + t];
        float4 hv1 = hb4[tile * 1024 + t + 512];

        // ---- generate w: row ir, j's [tile*64+jh, +8) ----
        {
            const int tb = tile * 64 + jh;
            const float4 p2a = *(const float4*)(p2s + tb);
            const float4 q2a = *(const float4*)(q2s + tb);
            const float4 p2b = *(const float4*)(p2s + tb + 4);
            const float4 q2b = *(const float4*)(q2s + tb + 4);
            float4 wq0, wq1;
            float w;
            w = fmaxf(p1r * p2a.x, q1r * q2a.x); if (av0.x <= 0) w = 0.f;
            zacc += w; wq0.x = to_tf32(w);
            w = fmaxf(p1r * p2a.y, q1r * q2a.y); if (av0.y <= 0) w = 0.f;
            zacc += w; wq0.y = to_tf32(w);
            w = fmaxf(p1r * p2a.z, q1r * q2a.z); if (av0.z <= 0) w = 0.f;
            zacc += w; wq0.z = to_tf32(w);
            w = fmaxf(p1r * p2a.w, q1r * q2a.w); if (av0.w <= 0) w = 0.f;
            zacc += w; wq0.w = to_tf32(w);
            w = fmaxf(p1r * p2b.x, q1r * q2b.x); if (av1.x <= 0) w = 0.f;
            zacc += w; wq1.x = to_tf32(w);
            w = fmaxf(p1r * p2b.y, q1r * q2b.y); if (av1.y <= 0) w = 0.f;
            zacc += w; wq1.y = to_tf32(w);
            w = fmaxf(p1r * p2b.z, q1r * q2b.z); if (av1.z <= 0) w = 0.f;
            zacc += w; wq1.z = to_tf32(w);
            w = fmaxf(p1r * p2b.w, q1r * q2b.w); if (av1.w <= 0) w = 0.f;
            zacc += w; wq1.w = to_tf32(w);
            float* wrow = ws + ir * 68 + jh;
            *(float4*)wrow       = wq0;
            *(float4*)(wrow + 4) = wq1;
        }

        // ---- stage h tile [64 j][64 o] (tf32), stride 72 ----
        hv0.x = to_tf32(hv0.x); hv0.y = to_tf32(hv0.y);
        hv0.z = to_tf32(hv0.z); hv0.w = to_tf32(hv0.w);
        ((float4*)hs)[(t >> 4) * 18 + (t & 15)] = hv0;
        hv1.x = to_tf32(hv1.x); hv1.y = to_tf32(hv1.y);
        hv1.z = to_tf32(hv1.z); hv1.w = to_tf32(hv1.w);
        ((float4*)hs)[((t + 512) >> 4) * 18 + (t & 15)] = hv1;

        __syncthreads();

        // ---- MMA: this warp's 2 k-steps (k-slice kq) ----
#pragma unroll
        for (int s = 0; s < 2; s++) {
            const int k0 = kbase + s * 8;
            uint32_t A[2][4];
#pragma unroll
            for (int mt = 0; mt < 2; mt++) {
                const int r0 = m0 + mt * 16 + g;
                A[mt][0] = __float_as_uint(ws[r0 * 68 + k0 + tid4]);
                A[mt][1] = __float_as_uint(ws[(r0 + 8) * 68 + k0 + tid4]);
                A[mt][2] = __float_as_uint(ws[r0 * 68 + k0 + tid4 + 4]);
                A[mt][3] = __float_as_uint(ws[(r0 + 8) * 68 + k0 + tid4 + 4]);
            }
#pragma unroll
            for (int nf = 0; nf < 4; nf++) {
                const int c0 = n0 + nf * 8 + g;
                const uint32_t b0 = __float_as_uint(hs[(k0 + tid4) * 72 + c0]);
                const uint32_t b1 = __float_as_uint(hs[(k0 + tid4 + 4) * 72 + c0]);
                mma_tf32(acc[0][nf], A[0], b0, b1);
                mma_tf32(acc[1][nf], A[1], b0, b1);
            }
        }
    }

    // ---- z: reduce the 8 j-block partials per row via shfl (t&7 groups) ----
    zacc += __shfl_xor_sync(0xffffffffu, zacc, 1);
    zacc += __shfl_xor_sync(0xffffffffu, zacc, 2);
    zacc += __shfl_xor_sync(0xffffffffu, zacc, 4);
    __syncthreads();    // all MMA done -> safe to overwrite ws/hs (accbuf)
    if ((t & 7) == 0) zs[ir] = zacc;

    // ---- k-reduction across the 4 k-slice warp groups into accbuf ----
#pragma unroll
    for (int ph = 0; ph < 4; ph++) {
        __syncthreads();
        if (kq == ph) {
#pragma unroll
            for (int mt = 0; mt < 2; mt++) {
#pragma unroll
                for (int nf = 0; nf < 4; nf++) {
                    const int rA = m0 + mt * 16 + g;
                    const int cc = n0 + nf * 8 + 2 * tid4;
                    float2* pA = (float2*)(accbuf + rA * 72 + cc);
                    float2* pB = (float2*)(accbuf + (rA + 8) * 72 + cc);
                    if (ph == 0) {
                        *pA = make_float2(acc[mt][nf][0], acc[mt][nf][1]);
                        *pB = make_float2(acc[mt][nf][2], acc[mt][nf][3]);
                    } else {
                        float2 vA = *pA, vB = *pB;
                        vA.x += acc[mt][nf][0]; vA.y += acc[mt][nf][1];
                        vB.x += acc[mt][nf][2]; vB.y += acc[mt][nf][3];
                        *pA = vA; *pB = vB;
                    }
                }
            }
        }
    }
    __syncthreads();

    // ---- final: normalize + ELU + store (8 elems/thread) ----
    {
        const int row = t >> 3;
        const int c0  = (t & 7) * 8;
        const float inv = 1.f / zs[row];
        const float* src = accbuf + row * 72 + c0;
        float4 r;
        float v;
        float4 x = *(const float4*)src;
        v = x.x * inv; r.x = (v > 0.f) ? v : expm1f(v);
        v = x.y * inv; r.y = (v > 0.f) ? v : expm1f(v);
        v = x.z * inv; r.z = (v > 0.f) ? v : expm1f(v);
        v = x.w * inv; r.w = (v > 0.f) ? v : expm1f(v);
        float4* op = (float4*)(out + ((size_t)(b * N_ + i0 + row)) * FO + c0);
        op[0] = r;
        x = *(const float4*)(src + 4);
        v = x.x * inv; r.x = (v > 0.f) ? v : expm1f(v);
        v = x.y * inv; r.y = (v > 0.f) ? v : expm1f(v);
        v = x.z * inv; r.z = (v > 0.f) ? v : expm1f(v);
        v = x.w * inv; r.w = (v > 0.f) ? v : expm1f(v);
        op[1] = r;
    }
}

// ---------------------------------------------------------------------------
extern "C" void kernel_launch(void* const* d_in, const int* in_sizes, int n_in,
                              void* d_out, int out_size) {
    const float* inp = (const float*)d_in[0];   // (16,1024,128) f32
    const int*   adj = (const int*)d_in[1];     // (16,1024,1024) i32
    const float* W   = (const float*)d_in[2];   // (128,64) f32
    const float* a   = (const float*)d_in[3];   // (128,1) f32
    float* out = (float*)d_out;                 // (16,1024,64) f32

    static int init = 0;
    if (!init) {
        cudaFuncSetAttribute(k_h_gemm, cudaFuncAttributeMaxDynamicSharedMemorySize,
                             SMEM_HG);
        cudaFuncSetAttribute(k_attn, cudaFuncAttributeMaxDynamicSharedMemorySize,
                             SMEM_ATTN);
        init = 1;
    }

    k_h_gemm<<<dim3(N_ / 64, B_), 256, SMEM_HG>>>(inp, W, a);
    k_attn<<<dim3(N_ / 64, B_), 512, SMEM_ATTN>>>(adj, out);
}

// round 10
// speedup vs baseline: 1.7132x; 1.2346x over previous
#include <cuda_runtime.h>
#include <cuda_bf16.h>
#include <math.h>
#include <stdint.h>

#define B_  16
#define N_  1024
#define FIN 128
#define FO  64
#define ALPHA_ 0.2f

// Scratch (device globals: no allocation allowed)
__device__ float  g_hs[B_ * 16 * 64 * 72];    // tf32 h, tiled+padded [b][tile][j][o(72)]
__device__ float2 g_pq1[B_ * N_];             // {exp(s1), exp(a*s1)}
__device__ float2 g_pq2[B_ * N_];             // {exp(s2), exp(a*s2)}

__device__ __forceinline__ float to_tf32(float x) {
    float r;
    asm("cvt.rna.tf32.f32 %0, %1;" : "=f"(r) : "f"(x));
    return r;
}
__device__ __forceinline__ void mma_tf32(float* d, const uint32_t* a,
                                         uint32_t b0, uint32_t b1) {
    asm volatile(
        "mma.sync.aligned.m16n8k8.row.col.f32.tf32.tf32.f32 "
        "{%0,%1,%2,%3}, {%4,%5,%6,%7}, {%8,%9}, {%0,%1,%2,%3};"
        : "+f"(d[0]), "+f"(d[1]), "+f"(d[2]), "+f"(d[3])
        : "r"(a[0]), "r"(a[1]), "r"(a[2]), "r"(a[3]), "r"(b0), "r"(b1));
}
__device__ __forceinline__ uint32_t smem_u32(const void* p) {
    uint32_t a;
    asm("{ .reg .u64 t; cvta.to.shared.u64 t, %1; cvt.u32.u64 %0, t; }"
        : "=r"(a) : "l"(p));
    return a;
}
#define CP_ASYNC16(dst_u32, src_ptr) \
    asm volatile("cp.async.cg.shared.global [%0], [%1], 16;" \
                 :: "r"(dst_u32), "l"(src_ptr))
#define CP_COMMIT() asm volatile("cp.async.commit_group;" ::: "memory")
#define CP_WAIT0()  asm volatile("cp.async.wait_group 0;" ::: "memory")

// k_attn smem layout (bytes). accbuf[64][72] reuses HS0 after the main loop.
#define HS0_OFF   0          // float hs[64][72] = 18432
#define HS1_OFF   18432
#define BITS0_OFF 36864      // uint32 bits[64][2] = 512
#define BITS1_OFF 37376
#define PQ2_OFF   37888      // float2 pq2s[1024] = 8192
#define ZP_OFF    46080      // float zp[4][64] = 1024
#define ZS_OFF    47104      // float zs[64] = 256
#define SMEM_ATTN 47360

#define SMEM_HG   66048      // sI 32K + sW 32K + sA 512

// ---------------------------------------------------------------------------
// Kernel 1: h = inp @ W -> g_hs (tf32, padded stride 72, tiled) + fused exps.
// ---------------------------------------------------------------------------
__global__ __launch_bounds__(256) void k_h_gemm(const float* __restrict__ inp,
                                                const float* __restrict__ W,
                                                const float* __restrict__ a) {
    extern __shared__ char sm1[];
    float* sI = (float*)sm1;             // [64][128]
    float* sW = (float*)(sm1 + 32768);   // [128][64]
    float* sA = (float*)(sm1 + 65536);   // [128]

    const int b    = blockIdx.y;
    const int bx   = blockIdx.x;         // tile index (64 rows per tile)
    const int row0 = bx * 64;
    const int t    = threadIdx.x;

#pragma unroll
    for (int k = 0; k < 8; k++)
        ((float4*)sW)[t + k * 256] = ((const float4*)W)[t + k * 256];
    const float4* ip = (const float4*)(inp + ((size_t)b * N_ + row0) * FIN);
#pragma unroll
    for (int k = 0; k < 8; k++)
        ((float4*)sI)[t + k * 256] = ip[t + k * 256];
    if (t < 128) sA[t] = a[t];
    __syncthreads();

    const int ot = t & 15;
    const int rt = t >> 4;
    const int lane = t & 31;

    float acc[4][4];
#pragma unroll
    for (int r = 0; r < 4; r++)
#pragma unroll
        for (int c = 0; c < 4; c++) acc[r][c] = 0.f;

#pragma unroll 4
    for (int k = 0; k < FIN; k++) {
        const float4 w4 = *(const float4*)(sW + k * FO + ot * 4);
#pragma unroll
        for (int r = 0; r < 4; r++) {
            const float iv = sI[(rt * 4 + r) * FIN + k];
            acc[r][0] += iv * w4.x;
            acc[r][1] += iv * w4.y;
            acc[r][2] += iv * w4.z;
            acc[r][3] += iv * w4.w;
        }
    }

    // store tf32 h into padded tiled layout
#pragma unroll
    for (int r = 0; r < 4; r++) {
        float4 wq;
        wq.x = to_tf32(acc[r][0]);
        wq.y = to_tf32(acc[r][1]);
        wq.z = to_tf32(acc[r][2]);
        wq.w = to_tf32(acc[r][3]);
        float* op = g_hs + ((size_t)(b * 16 + bx) * 64 + rt * 4 + r) * 72 + ot * 4;
        *(float4*)op = wq;
    }

    // fused scores
    float s1p[4], s2p[4];
#pragma unroll
    for (int r = 0; r < 4; r++) {
        float v1 = 0.f, v2 = 0.f;
#pragma unroll
        for (int c = 0; c < 4; c++) {
            v1 += acc[r][c] * sA[ot * 4 + c];
            v2 += acc[r][c] * sA[64 + ot * 4 + c];
        }
        s1p[r] = v1; s2p[r] = v2;
    }
#pragma unroll
    for (int off = 8; off > 0; off >>= 1) {
#pragma unroll
        for (int r = 0; r < 4; r++) {
            s1p[r] += __shfl_xor_sync(0xffffffffu, s1p[r], off);
            s2p[r] += __shfl_xor_sync(0xffffffffu, s2p[r], off);
        }
    }
    if ((lane & 15) == 0) {
#pragma unroll
        for (int r = 0; r < 4; r++) {
            const int gi = b * N_ + row0 + rt * 4 + r;
            g_pq1[gi] = make_float2(__expf(s1p[r]), __expf(ALPHA_ * s1p[r]));
            g_pq2[gi] = make_float2(__expf(s2p[r]), __expf(ALPHA_ * s2p[r]));
        }
    }
}

// ---------------------------------------------------------------------------
// Kernel 2: attention via mma.sync tf32; A-operand generated IN REGISTERS
// (fragment layout), no ws smem round-trip. adj staged as ballot bitmasks.
// h staged via cp.async from pre-tf32 g_hs (double-buffered).
// CTA: 64 i x 64 o, 256 thr, 8 warps = 2m x 4k, warp tile 32m x 64n x 16k.
// ---------------------------------------------------------------------------
__global__ __launch_bounds__(256, 2) void k_attn(const int* __restrict__ adj,
                                                 float* __restrict__ out) {
    extern __shared__ char sm[];
    float2*   pq2s = (float2*)(sm + PQ2_OFF);
    float*    zp   = (float*)(sm + ZP_OFF);     // [4][64]
    float*    zs   = (float*)(sm + ZS_OFF);
    float*    accbuf = (float*)sm;              // [64][72] (reuse after loop)
    const uint32_t smbase = smem_u32(sm);

    const int b  = blockIdx.y;
    const int i0 = blockIdx.x * 64;
    const int t  = threadIdx.x;
    const int wid  = t >> 5;
    const int lane = t & 31;
    const int g    = lane >> 2;
    const int tid4 = lane & 3;
    const int kq   = wid >> 1;          // 0..3 (k-slice of 16)
    const int m0   = (wid & 1) * 32;    // m-quad

    // tables
    for (int idx = t; idx < N_; idx += 256) pq2s[idx] = g_pq2[b * N_ + idx];
    float p1r[4], q1r[4];
#pragma unroll
    for (int u = 0; u < 4; u++) {
        const float2 pq = g_pq1[b * N_ + i0 + m0 + u * 8 + g];
        p1r[u] = pq.x; q1r[u] = pq.y;
    }

    // adj flat mapping: thread t covers col (t&63), rows (t>>6)+4k, k=0..15
    const int* adjp = adj + (size_t)b * N_ * N_ + (size_t)(i0 + (t >> 6)) * N_ + (t & 63);
    const int rw0  = wid >> 1;          // ballot row base (t>>6 == wid>>1)
    const int wsel = wid & 1;           // which 32-col word this warp covers

    // ---- prologue: bits(0) + B(0) ----
    {
        uint32_t* bits = (uint32_t*)(sm + BITS0_OFF);
#pragma unroll
        for (int k = 0; k < 16; k++) {
            const int av = adjp[(size_t)(4 * k) * N_];
            const uint32_t msk = __ballot_sync(0xffffffffu, av > 0);
            if (lane == 0) bits[(rw0 + 4 * k) * 2 + wsel] = msk;
        }
        const float4* src = (const float4*)(g_hs + (size_t)(b * 16) * 4608);
        const uint32_t dst = smbase + HS0_OFF;
#pragma unroll
        for (int k = 0; k < 4; k++)
            CP_ASYNC16(dst + (t + 256 * k) * 16, src + t + 256 * k);
        if (t < 128) CP_ASYNC16(dst + (t + 1024) * 16, src + t + 1024);
        CP_COMMIT();
    }
    CP_WAIT0();
    __syncthreads();

    float acc[2][8][4];
#pragma unroll
    for (int mt = 0; mt < 2; mt++)
#pragma unroll
        for (int nf = 0; nf < 8; nf++)
#pragma unroll
            for (int c = 0; c < 4; c++) acc[mt][nf][c] = 0.f;
    float zac[4] = {0.f, 0.f, 0.f, 0.f};

    for (int tile = 0; tile < 16; tile++) {
        const int cur = tile & 1;
        float*    hs_   = (float*)(sm + (cur ? HS1_OFF : HS0_OFF));
        uint32_t* bits_ = (uint32_t*)(sm + (cur ? BITS1_OFF : BITS0_OFF));

        // issue next-tile global loads first
        int anx[16];
        if (tile < 15) {
#pragma unroll
            for (int k = 0; k < 16; k++)
                anx[k] = adjp[(size_t)(4 * k) * N_ + (tile + 1) * 64];
            const float4* src = (const float4*)(g_hs + (size_t)(b * 16 + tile + 1) * 4608);
            const uint32_t dst = smbase + (cur ? HS0_OFF : HS1_OFF);
#pragma unroll
            for (int k = 0; k < 4; k++)
                CP_ASYNC16(dst + (t + 256 * k) * 16, src + t + 256 * k);
            if (t < 128) CP_ASYNC16(dst + (t + 1024) * 16, src + t + 1024);
            CP_COMMIT();
        }

        // ---- gen A fragments in registers (w in tf32 bits) ----
        uint32_t word[4];
#pragma unroll
        for (int u = 0; u < 4; u++)
            word[u] = bits_[(m0 + u * 8 + g) * 2 + (kq >> 1)];

        uint32_t wb[4][4];   // [u][s*2+v]
#pragma unroll
        for (int sv = 0; sv < 4; sv++) {
            const int s = sv >> 1, v = sv & 1;
            const int c = (kq << 4) + s * 8 + tid4 + 4 * v;
            const float2 pq = pq2s[tile * 64 + c];
            const int bit = c & 31;
#pragma unroll
            for (int u = 0; u < 4; u++) {
                float w = ((word[u] >> bit) & 1u)
                              ? fmaxf(p1r[u] * pq.x, q1r[u] * pq.y) : 0.f;
                zac[u] += w;
                wb[u][sv] = __float_as_uint(to_tf32(w));
            }
        }

        // pack + store next-tile bits (adj LDGs have had gen-phase to land)
        if (tile < 15) {
            uint32_t* bn = (uint32_t*)(sm + (cur ? BITS0_OFF : BITS1_OFF));
#pragma unroll
            for (int k = 0; k < 16; k++) {
                const uint32_t msk = __ballot_sync(0xffffffffu, anx[k] > 0);
                if (lane == 0) bn[(rw0 + 4 * k) * 2 + wsel] = msk;
            }
        }

        // ---- MMA: 2 k-steps, full n=64 ----
#pragma unroll
        for (int s = 0; s < 2; s++) {
            const int kt = (kq << 4) + s * 8 + tid4;
            uint32_t A0[4] = {wb[0][s * 2], wb[1][s * 2], wb[0][s * 2 + 1], wb[1][s * 2 + 1]};
            uint32_t A1[4] = {wb[2][s * 2], wb[3][s * 2], wb[2][s * 2 + 1], wb[3][s * 2 + 1]};
#pragma unroll
            for (int nf = 0; nf < 8; nf++) {
                const int c0 = nf * 8 + g;
                const uint32_t b0 = __float_as_uint(hs_[kt * 72 + c0]);
                const uint32_t b1 = __float_as_uint(hs_[(kt + 4) * 72 + c0]);
                mma_tf32(acc[0][nf], A0, b0, b1);
                mma_tf32(acc[1][nf], A1, b0, b1);
            }
        }

        CP_WAIT0();
        __syncthreads();
    }

    // ---- z: quad shfl-reduce then per-kq slots ----
#pragma unroll
    for (int u = 0; u < 4; u++) {
        zac[u] += __shfl_xor_sync(0xffffffffu, zac[u], 1);
        zac[u] += __shfl_xor_sync(0xffffffffu, zac[u], 2);
    }
    if (tid4 == 0) {
#pragma unroll
        for (int u = 0; u < 4; u++)
            zp[kq * 64 + m0 + u * 8 + g] = zac[u];
    }
    __syncthreads();
    if (t < 64) zs[t] = (zp[t] + zp[64 + t]) + (zp[128 + t] + zp[192 + t]);

    // ---- k-reduction across the 4 kq groups into accbuf (reuses HS0) ----
#pragma unroll
    for (int ph = 0; ph < 4; ph++) {
        __syncthreads();
        if (kq == ph) {
#pragma unroll
            for (int mt = 0; mt < 2; mt++) {
#pragma unroll
                for (int nf = 0; nf < 8; nf++) {
                    const int rA = m0 + mt * 16 + g;
                    const int cc = nf * 8 + 2 * tid4;
                    float2* pA = (float2*)(accbuf + rA * 72 + cc);
                    float2* pB = (float2*)(accbuf + (rA + 8) * 72 + cc);
                    if (ph == 0) {
                        *pA = make_float2(acc[mt][nf][0], acc[mt][nf][1]);
                        *pB = make_float2(acc[mt][nf][2], acc[mt][nf][3]);
                    } else {
                        float2 vA = *pA, vB = *pB;
                        vA.x += acc[mt][nf][0]; vA.y += acc[mt][nf][1];
                        vB.x += acc[mt][nf][2]; vB.y += acc[mt][nf][3];
                        *pA = vA; *pB = vB;
                    }
                }
            }
        }
    }
    __syncthreads();

    // ---- final: normalize + ELU + store (16 elems/thread) ----
    {
        const int row = t >> 2;
        const int c0  = (t & 3) * 16;
        const float inv = 1.f / zs[row];
        const float* src = accbuf + row * 72 + c0;
        float4* op = (float4*)(out + ((size_t)(b * N_ + i0 + row)) * FO + c0);
#pragma unroll
        for (int q = 0; q < 4; q++) {
            float4 x = *(const float4*)(src + 4 * q);
            float4 r;
            float v;
            v = x.x * inv; r.x = (v > 0.f) ? v : expm1f(v);
            v = x.y * inv; r.y = (v > 0.f) ? v : expm1f(v);
            v = x.z * inv; r.z = (v > 0.f) ? v : expm1f(v);
            v = x.w * inv; r.w = (v > 0.f) ? v : expm1f(v);
            op[q] = r;
        }
    }
}

// ---------------------------------------------------------------------------
extern "C" void kernel_launch(void* const* d_in, const int* in_sizes, int n_in,
                              void* d_out, int out_size) {
    const float* inp = (const float*)d_in[0];   // (16,1024,128) f32
    const int*   adj = (const int*)d_in[1];     // (16,1024,1024) i32
    const float* W   = (const float*)d_in[2];   // (128,64) f32
    const float* a   = (const float*)d_in[3];   // (128,1) f32
    float* out = (float*)d_out;                 // (16,1024,64) f32

    static int init = 0;
    if (!init) {
        cudaFuncSetAttribute(k_h_gemm, cudaFuncAttributeMaxDynamicSharedMemorySize,
                             SMEM_HG);
        cudaFuncSetAttribute(k_attn, cudaFuncAttributeMaxDynamicSharedMemorySize,
                             SMEM_ATTN);
        init = 1;
    }

    k_h_gemm<<<dim3(N_ / 64, B_), 256, SMEM_HG>>>(inp, W, a);
    k_attn<<<dim3(N_ / 64, B_), 256, SMEM_ATTN>>>(adj, out);
}

// round 11
// speedup vs baseline: 1.7388x; 1.0149x over previous
#include <cuda_runtime.h>
#include <cuda_bf16.h>
#include <math.h>
#include <stdint.h>

#define B_  16
#define N_  1024
#define FIN 128
#define FO  64
#define ALPHA_ 0.2f

// Scratch (device globals: no allocation allowed)
// g_hs: tf32 h in MMA B-fragment order, per tile 2048 float2:
//   pair f: blk=f>>5 (koct*8+nf), l=f&31 -> {h[koct*8+(l&3)][nf*8+(l>>2)],
//                                            h[koct*8+4+(l&3)][nf*8+(l>>2)]}
__device__ float2 g_hs[B_ * 16 * 2048];       // 4 MB
__device__ float2 g_pq1[B_ * N_];             // {exp(s1), exp(a*s1)}
__device__ float2 g_pq2[B_ * N_];             // {exp(s2), exp(a*s2)}

__device__ __forceinline__ float to_tf32(float x) {
    float r;
    asm("cvt.rna.tf32.f32 %0, %1;" : "=f"(r) : "f"(x));
    return r;
}
__device__ __forceinline__ void mma_tf32(float* d, const uint32_t* a,
                                         uint32_t b0, uint32_t b1) {
    asm volatile(
        "mma.sync.aligned.m16n8k8.row.col.f32.tf32.tf32.f32 "
        "{%0,%1,%2,%3}, {%4,%5,%6,%7}, {%8,%9}, {%0,%1,%2,%3};"
        : "+f"(d[0]), "+f"(d[1]), "+f"(d[2]), "+f"(d[3])
        : "r"(a[0]), "r"(a[1]), "r"(a[2]), "r"(a[3]), "r"(b0), "r"(b1));
}
__device__ __forceinline__ uint32_t smem_u32(const void* p) {
    uint32_t a;
    asm("{ .reg .u64 t; cvta.to.shared.u64 t, %1; cvt.u32.u64 %0, t; }"
        : "=r"(a) : "l"(p));
    return a;
}
#define CP_ASYNC16(dst_u32, src_ptr) \
    asm volatile("cp.async.cg.shared.global [%0], [%1], 16;" \
                 :: "r"(dst_u32), "l"(src_ptr))
#define CP_COMMIT() asm volatile("cp.async.commit_group;" ::: "memory")
#define CP_WAIT0()  asm volatile("cp.async.wait_group 0;" ::: "memory")

// k_attn smem layout (bytes). accbuf[64][72] (18432 B) overlays HS0+HS1.
#define HS0_OFF   0          // float2 hs[2048] = 16384
#define HS1_OFF   16384
#define BITS0_OFF 32768      // uint32 bits[64][2] = 512
#define BITS1_OFF 33280
#define PQ2_OFF   33792      // float2 pq2s[1024] = 8192
#define ZP_OFF    41984      // float zp[4][64] = 1024
#define ZS_OFF    43008      // float zs[64] = 256
#define SMEM_ATTN 43264

#define SMEM_HG   66048      // sI 32K + sW 32K + sA 512 (sT reuses sI)

// ---------------------------------------------------------------------------
// Kernel 1: h = inp @ W -> g_hs (tf32, B-fragment order) + fused exps.
// ---------------------------------------------------------------------------
__global__ __launch_bounds__(256) void k_h_gemm(const float* __restrict__ inp,
                                                const float* __restrict__ W,
                                                const float* __restrict__ a) {
    extern __shared__ char sm1[];
    float* sI = (float*)sm1;             // [64][128]
    float* sW = (float*)(sm1 + 32768);   // [128][64]
    float* sA = (float*)(sm1 + 65536);   // [128]
    float* sT = (float*)sm1;             // [64][68] transpose stage (reuses sI)

    const int b    = blockIdx.y;
    const int bx   = blockIdx.x;         // tile index (64 rows per tile)
    const int row0 = bx * 64;
    const int t    = threadIdx.x;

#pragma unroll
    for (int k = 0; k < 8; k++)
        ((float4*)sW)[t + k * 256] = ((const float4*)W)[t + k * 256];
    const float4* ip = (const float4*)(inp + ((size_t)b * N_ + row0) * FIN);
#pragma unroll
    for (int k = 0; k < 8; k++)
        ((float4*)sI)[t + k * 256] = ip[t + k * 256];
    if (t < 128) sA[t] = a[t];
    __syncthreads();

    const int ot = t & 15;
    const int rt = t >> 4;
    const int lane = t & 31;

    float acc[4][4];
#pragma unroll
    for (int r = 0; r < 4; r++)
#pragma unroll
        for (int c = 0; c < 4; c++) acc[r][c] = 0.f;

#pragma unroll 4
    for (int k = 0; k < FIN; k++) {
        const float4 w4 = *(const float4*)(sW + k * FO + ot * 4);
#pragma unroll
        for (int r = 0; r < 4; r++) {
            const float iv = sI[(rt * 4 + r) * FIN + k];
            acc[r][0] += iv * w4.x;
            acc[r][1] += iv * w4.y;
            acc[r][2] += iv * w4.z;
            acc[r][3] += iv * w4.w;
        }
    }

    // fused scores (uses acc before staging)
    float s1p[4], s2p[4];
#pragma unroll
    for (int r = 0; r < 4; r++) {
        float v1 = 0.f, v2 = 0.f;
#pragma unroll
        for (int c = 0; c < 4; c++) {
            v1 += acc[r][c] * sA[ot * 4 + c];
            v2 += acc[r][c] * sA[64 + ot * 4 + c];
        }
        s1p[r] = v1; s2p[r] = v2;
    }
#pragma unroll
    for (int off = 8; off > 0; off >>= 1) {
#pragma unroll
        for (int r = 0; r < 4; r++) {
            s1p[r] += __shfl_xor_sync(0xffffffffu, s1p[r], off);
            s2p[r] += __shfl_xor_sync(0xffffffffu, s2p[r], off);
        }
    }

    // stage tf32 h into sT (stride 68), then write fragment-ordered g_hs
    __syncthreads();   // done reading sI
#pragma unroll
    for (int r = 0; r < 4; r++) {
        float4 wq;
        wq.x = to_tf32(acc[r][0]);
        wq.y = to_tf32(acc[r][1]);
        wq.z = to_tf32(acc[r][2]);
        wq.w = to_tf32(acc[r][3]);
        *(float4*)(sT + (rt * 4 + r) * 68 + ot * 4) = wq;
    }
    __syncthreads();

    {
        float2* dst = g_hs + (size_t)(b * 16 + bx) * 2048;
#pragma unroll
        for (int q = 0; q < 8; q++) {
            const int f   = q * 256 + t;
            const int l   = f & 31;
            const int blk = f >> 5;          // koct*8 + nf
            const int j0  = (blk >> 3) * 8 + (l & 3);
            const int c   = (blk & 7) * 8 + (l >> 2);
            float2 v;
            v.x = sT[j0 * 68 + c];
            v.y = sT[(j0 + 4) * 68 + c];
            dst[f] = v;
        }
    }

    if ((lane & 15) == 0) {
#pragma unroll
        for (int r = 0; r < 4; r++) {
            const int gi = b * N_ + row0 + rt * 4 + r;
            g_pq1[gi] = make_float2(__expf(s1p[r]), __expf(ALPHA_ * s1p[r]));
            g_pq2[gi] = make_float2(__expf(s2p[r]), __expf(ALPHA_ * s2p[r]));
        }
    }
}

// ---------------------------------------------------------------------------
// Kernel 2: attention via mma.sync tf32; A generated in registers,
// B staged pre-fragmented (LDS.64), adj as ballot bitmasks (packed post-MMA).
// CTA: 64 i x 64 o, 256 thr, 8 warps = 2m x 4k, warp tile 32m x 64n x 16k.
// ---------------------------------------------------------------------------
__global__ __launch_bounds__(256, 2) void k_attn(const int* __restrict__ adj,
                                                 float* __restrict__ out) {
    extern __shared__ char sm[];
    float2*   pq2s = (float2*)(sm + PQ2_OFF);
    float*    zp   = (float*)(sm + ZP_OFF);     // [4][64]
    float*    zs   = (float*)(sm + ZS_OFF);
    float*    accbuf = (float*)sm;              // [64][72] (reuse after loop)
    const uint32_t smbase = smem_u32(sm);

    const int b  = blockIdx.y;
    const int i0 = blockIdx.x * 64;
    const int t  = threadIdx.x;
    const int wid  = t >> 5;
    const int lane = t & 31;
    const int g    = lane >> 2;
    const int tid4 = lane & 3;
    const int kq   = wid >> 1;          // 0..3 (k-slice of 16)
    const int m0   = (wid & 1) * 32;    // m-quad

    // tables
    for (int idx = t; idx < N_; idx += 256) pq2s[idx] = g_pq2[b * N_ + idx];
    float p1r[4], q1r[4];
#pragma unroll
    for (int u = 0; u < 4; u++) {
        const float2 pq = g_pq1[b * N_ + i0 + m0 + u * 8 + g];
        p1r[u] = pq.x; q1r[u] = pq.y;
    }

    // adj flat mapping: thread t covers col (t&63), rows (t>>6)+4k, k=0..15
    const int* adjp = adj + (size_t)b * N_ * N_ + (size_t)(i0 + (t >> 6)) * N_ + (t & 63);
    const int rw0  = wid >> 1;          // ballot row base (t>>6 == wid>>1)
    const int wsel = wid & 1;           // which 32-col word this warp covers

    // ---- prologue: bits(0) + B(0) ----
    {
        uint32_t* bits = (uint32_t*)(sm + BITS0_OFF);
#pragma unroll
        for (int k = 0; k < 16; k++) {
            const int av = adjp[(size_t)(4 * k) * N_];
            const uint32_t msk = __ballot_sync(0xffffffffu, av > 0);
            if (lane == 0) bits[(rw0 + 4 * k) * 2 + wsel] = msk;
        }
        const float4* src = (const float4*)(g_hs + (size_t)(b * 16) * 2048);
        const uint32_t dst = smbase + HS0_OFF;
#pragma unroll
        for (int k = 0; k < 4; k++)
            CP_ASYNC16(dst + (t + 256 * k) * 16, src + t + 256 * k);
        CP_COMMIT();
    }
    CP_WAIT0();
    __syncthreads();

    float acc[2][8][4];
#pragma unroll
    for (int mt = 0; mt < 2; mt++)
#pragma unroll
        for (int nf = 0; nf < 8; nf++)
#pragma unroll
            for (int c = 0; c < 4; c++) acc[mt][nf][c] = 0.f;
    float zac[4] = {0.f, 0.f, 0.f, 0.f};

    for (int tile = 0; tile < 16; tile++) {
        const int cur = tile & 1;
        const float2*   hs_   = (const float2*)(sm + (cur ? HS1_OFF : HS0_OFF));
        const uint32_t* bits_ = (const uint32_t*)(sm + (cur ? BITS1_OFF : BITS0_OFF));

        // issue next-tile global loads first
        int anx[16];
        if (tile < 15) {
#pragma unroll
            for (int k = 0; k < 16; k++)
                anx[k] = adjp[(size_t)(4 * k) * N_ + (tile + 1) * 64];
            const float4* src = (const float4*)(g_hs + (size_t)(b * 16 + tile + 1) * 2048);
            const uint32_t dst = smbase + (cur ? HS0_OFF : HS1_OFF);
#pragma unroll
            for (int k = 0; k < 4; k++)
                CP_ASYNC16(dst + (t + 256 * k) * 16, src + t + 256 * k);
            CP_COMMIT();
        }

        // ---- gen A fragments in registers (w in tf32 bits) ----
        uint32_t word[4];
#pragma unroll
        for (int u = 0; u < 4; u++)
            word[u] = bits_[(m0 + u * 8 + g) * 2 + (kq >> 1)];

        uint32_t wb[4][4];   // [u][s*2+v]
#pragma unroll
        for (int sv = 0; sv < 4; sv++) {
            const int s = sv >> 1, v = sv & 1;
            const int c = (kq << 4) + s * 8 + tid4 + 4 * v;
            const float2 pq = pq2s[tile * 64 + c];
            const int bit = c & 31;
#pragma unroll
            for (int u = 0; u < 4; u++) {
                float w = ((word[u] >> bit) & 1u)
                              ? fmaxf(p1r[u] * pq.x, q1r[u] * pq.y) : 0.f;
                zac[u] += w;
                wb[u][sv] = __float_as_uint(to_tf32(w));
            }
        }

        // ---- MMA: 2 k-steps, full n=64, B via pre-fragmented LDS.64 ----
#pragma unroll
        for (int s = 0; s < 2; s++) {
            const int koct = (kq << 1) + s;
            const float2* bp = hs_ + koct * 256 + lane;
            uint32_t A0[4] = {wb[0][s * 2], wb[1][s * 2], wb[0][s * 2 + 1], wb[1][s * 2 + 1]};
            uint32_t A1[4] = {wb[2][s * 2], wb[3][s * 2], wb[2][s * 2 + 1], wb[3][s * 2 + 1]};
#pragma unroll
            for (int nf = 0; nf < 8; nf++) {
                const float2 bb = bp[nf * 32];
                const uint32_t b0 = __float_as_uint(bb.x);
                const uint32_t b1 = __float_as_uint(bb.y);
                mma_tf32(acc[0][nf], A0, b0, b1);
                mma_tf32(acc[1][nf], A1, b0, b1);
            }
        }

        // ---- pack + store next-tile bits (adj LDGs now had gen+MMA to land) ----
        if (tile < 15) {
            uint32_t* bn = (uint32_t*)(sm + (cur ? BITS0_OFF : BITS1_OFF));
#pragma unroll
            for (int k = 0; k < 16; k++) {
                const uint32_t msk = __ballot_sync(0xffffffffu, anx[k] > 0);
                if (lane == 0) bn[(rw0 + 4 * k) * 2 + wsel] = msk;
            }
        }

        CP_WAIT0();
        __syncthreads();
    }

    // ---- z: quad shfl-reduce then per-kq slots ----
#pragma unroll
    for (int u = 0; u < 4; u++) {
        zac[u] += __shfl_xor_sync(0xffffffffu, zac[u], 1);
        zac[u] += __shfl_xor_sync(0xffffffffu, zac[u], 2);
    }
    if (tid4 == 0) {
#pragma unroll
        for (int u = 0; u < 4; u++)
            zp[kq * 64 + m0 + u * 8 + g] = zac[u];
    }
    __syncthreads();
    if (t < 64) zs[t] = (zp[t] + zp[64 + t]) + (zp[128 + t] + zp[192 + t]);

    // ---- k-reduction across the 4 kq groups into accbuf ----
#pragma unroll
    for (int ph = 0; ph < 4; ph++) {
        __syncthreads();
        if (kq == ph) {
#pragma unroll
            for (int mt = 0; mt < 2; mt++) {
#pragma unroll
                for (int nf = 0; nf < 8; nf++) {
                    const int rA = m0 + mt * 16 + g;
                    const int cc = nf * 8 + 2 * tid4;
                    float2* pA = (float2*)(accbuf + rA * 72 + cc);
                    float2* pB = (float2*)(accbuf + (rA + 8) * 72 + cc);
                    if (ph == 0) {
                        *pA = make_float2(acc[mt][nf][0], acc[mt][nf][1]);
                        *pB = make_float2(acc[mt][nf][2], acc[mt][nf][3]);
                    } else {
                        float2 vA = *pA, vB = *pB;
                        vA.x += acc[mt][nf][0]; vA.y += acc[mt][nf][1];
                        vB.x += acc[mt][nf][2]; vB.y += acc[mt][nf][3];
                        *pA = vA; *pB = vB;
                    }
                }
            }
        }
    }
    __syncthreads();

    // ---- final: normalize + ELU + store (16 elems/thread) ----
    {
        const int row = t >> 2;
        const int c0  = (t & 3) * 16;
        const float inv = 1.f / zs[row];
        const float* src = accbuf + row * 72 + c0;
        float4* op = (float4*)(out + ((size_t)(b * N_ + i0 + row)) * FO + c0);
#pragma unroll
        for (int q = 0; q < 4; q++) {
            float4 x = *(const float4*)(src + 4 * q);
            float4 r;
            float v;
            v = x.x * inv; r.x = (v > 0.f) ? v : expm1f(v);
            v = x.y * inv; r.y = (v > 0.f) ? v : expm1f(v);
            v = x.z * inv; r.z = (v > 0.f) ? v : expm1f(v);
            v = x.w * inv; r.w = (v > 0.f) ? v : expm1f(v);
            op[q] = r;
        }
    }
}

// ---------------------------------------------------------------------------
extern "C" void kernel_launch(void* const* d_in, const int* in_sizes, int n_in,
                              void* d_out, int out_size) {
    const float* inp = (const float*)d_in[0];   // (16,1024,128) f32
    const int*   adj = (const int*)d_in[1];     // (16,1024,1024) i32
    const float* W   = (const float*)d_in[2];   // (128,64) f32
    const float* a   = (const float*)d_in[3];   // (128,1) f32
    float* out = (float*)d_out;                 // (16,1024,64) f32

    static int init = 0;
    if (!init) {
        cudaFuncSetAttribute(k_h_gemm, cudaFuncAttributeMaxDynamicSharedMemorySize,
                             SMEM_HG);
        cudaFuncSetAttribute(k_attn, cudaFuncAttributeMaxDynamicSharedMemorySize,
                             SMEM_ATTN);
        init = 1;
    }

    k_h_gemm<<<dim3(N_ / 64, B_), 256, SMEM_HG>>>(inp, W, a);
    k_attn<<<dim3(N_ / 64, B_), 256, SMEM_ATTN>>>(adj, out);
}